// round 4
// baseline (speedup 1.0000x reference)
#include <cuda_runtime.h>
#include <cstdint>

// logits [16, 2048, 1] fp32, seq_len [16] i32, out [16, 2048, 2048] fp32.
#define BB 16
#define TT 2048
#define RPB 8          // rows per block
#define THREADS 256
#define TBL 1024       // table resolution over t = |s_i - s_j| in [0,1)

// scratch (device globals; no allocation allowed)
__device__ float g_scores[BB * TT];   // sigmoid(logits)
__device__ float g_f[TBL + 1];        // f(k/TBL) = exp(sigmoid((0.5 - t)*10))

// Tiny prep kernel: 32K sigmoids + 1025 table nodes. ~2us incl. launch.
__global__ void prep_kernel(const float* __restrict__ logits) {
    const int idx = blockIdx.x * blockDim.x + threadIdx.x;
    if (idx < BB * TT) {
        const float x = logits[idx];
        g_scores[idx] = __fdividef(1.0f, 1.0f + __expf(-x));
    }
    if (idx <= TBL) {
        const float t   = (float)idx * (1.0f / TBL);
        const float z   = (0.5f - t) * 10.0f;
        const float sig = __fdividef(1.0f, 1.0f + __expf(-z));
        g_f[idx] = __expf(sig);
    }
}

// Main kernel: MUFU-free inner loop via interpolated table lookup.
// Max-free softmax is exact: f(t) in (1, e); masked entries exact 0.
__global__ __launch_bounds__(THREADS) void row_softmax_kernel(
    const int* __restrict__ seq_len,
    float* __restrict__ out)
{
    __shared__ float  s_scores[TT];
    __shared__ float2 s_table[TBL];           // (base, slope)
    __shared__ float  s_red[THREADS / 32];
    __shared__ float  s_inv;

    const int b    = blockIdx.y;
    const int row0 = blockIdx.x * RPB;
    const int tid  = threadIdx.x;
    const int L    = seq_len[b];

    // stage scores (L2-hit, coalesced float4)
    {
        const float4* src = reinterpret_cast<const float4*>(g_scores + b * TT);
        #pragma unroll
        for (int k = 0; k < (TT / 4) / THREADS; k++)
            reinterpret_cast<float4*>(s_scores)[tid + k * THREADS] =
                src[tid + k * THREADS];
    }
    // stage table with precomputed slope (L2/L1-hit)
    #pragma unroll
    for (int k = tid; k < TBL; k += THREADS) {
        const float a = g_f[k];
        s_table[k] = make_float2(a, g_f[k + 1] - a);
    }
    __syncthreads();

    for (int r = 0; r < RPB; r++) {
        const int i = row0 + r;
        float* orow = out + ((size_t)b * TT + (size_t)i) * TT;

        if (i >= L) {
            // invalid row -> all zeros (uniform branch; no syncs inside)
            const float4 z = make_float4(0.f, 0.f, 0.f, 0.f);
            #pragma unroll
            for (int k = 0; k < (TT / 4) / THREADS; k++)
                __stcs(reinterpret_cast<float4*>(orow) + tid + k * THREADS, z);
            continue;
        }

        const float s_i = s_scores[i];
        float e[8];
        float psum = 0.f;

        #pragma unroll
        for (int c = 0; c < 2; c++) {
            const int jbase = c * 1024 + tid * 4;
            const float4 sv = reinterpret_cast<const float4*>(s_scores)[c * THREADS + tid];
            const float sj[4] = {sv.x, sv.y, sv.z, sv.w};
            if (jbase + 3 < L) {
                // fully valid chunk: no predication
                #pragma unroll
                for (int q = 0; q < 4; q++) {
                    const float u    = fabsf(s_i - sj[q]) * (float)TBL; // t in [0,1)
                    const int   k    = (int)u;                          // trunc, k <= TBL-1
                    const float frac = u - (float)k;
                    const float2 tb  = s_table[k];
                    const float ev   = fmaf(tb.y, frac, tb.x);
                    e[c * 4 + q] = ev;
                    psum += ev;
                }
            } else {
                #pragma unroll
                for (int q = 0; q < 4; q++) {
                    const int j = jbase + q;
                    float ev = 0.f;
                    if (j < L) {
                        const float u    = fabsf(s_i - sj[q]) * (float)TBL;
                        const int   k    = (int)u;
                        const float frac = u - (float)k;
                        const float2 tb  = s_table[k];
                        ev = fmaf(tb.y, frac, tb.x);
                    }
                    e[c * 4 + q] = ev;
                    psum += ev;
                }
            }
        }

        // block reduction of psum
        #pragma unroll
        for (int off = 16; off > 0; off >>= 1)
            psum += __shfl_xor_sync(0xFFFFFFFFu, psum, off);
        if ((tid & 31) == 0) s_red[tid >> 5] = psum;
        __syncthreads();
        if (tid == 0) {
            float tot = 0.f;
            #pragma unroll
            for (int w = 0; w < THREADS / 32; w++) tot += s_red[w];
            s_inv = __fdividef(1.0f, tot);
        }
        __syncthreads();
        const float inv = s_inv;

        // normalized evict-streaming stores (float4, coalesced)
        #pragma unroll
        for (int c = 0; c < 2; c++) {
            const float4 v = make_float4(e[c * 4 + 0] * inv, e[c * 4 + 1] * inv,
                                         e[c * 4 + 2] * inv, e[c * 4 + 3] * inv);
            __stcs(reinterpret_cast<float4*>(orow) + c * THREADS + tid, v);
        }
        __syncthreads();   // protect s_red/s_inv before next row
    }
}

extern "C" void kernel_launch(void* const* d_in, const int* in_sizes, int n_in,
                              void* d_out, int out_size) {
    const float* logits  = (const float*)d_in[0];   // [16, 2048, 1] fp32
    const int*   seq_len = (const int*)d_in[1];     // [16] i32
    float*       out     = (float*)d_out;           // [16, 2048, 2048] fp32

    prep_kernel<<<(BB * TT + 255) / 256, 256>>>(logits);

    dim3 grid(TT / RPB, BB);
    row_softmax_kernel<<<grid, THREADS>>>(seq_len, out);
}

// round 5
// speedup vs baseline: 1.1454x; 1.1454x over previous
#include <cuda_runtime.h>
#include <cstdint>

// logits [16, 2048, 1] fp32, seq_len [16] i32, out [16, 2048, 2048] fp32.
#define BB 16
#define TT 2048
#define WPB 8                 // warps per block; one output row per warp
#define THREADS (WPB * 32)

// Fully fused, barrier-free after staging. Each block:
//   1. computes sigmoid(logits[b,:]) into smem (one __syncthreads),
//   2. each WARP independently handles one row: compute 64 e-values in regs,
//      butterfly shfl reduction (no block sync), streaming float4 stores.
//
// Max-free softmax is exact: rel values in (0.0067, 0.9933) -> exp in (1, e),
// no overflow; masked entries exactly 0, matching the reference's fp32
// exp(-1e9 - max) == 0.
__global__ __launch_bounds__(THREADS, 3) void fused_kernel(
    const float* __restrict__ logits,
    const int* __restrict__ seq_len,
    float* __restrict__ out)
{
    __shared__ float s_scores[TT];

    const int b    = blockIdx.y;
    const int tid  = threadIdx.x;
    const int warp = tid >> 5;
    const int lane = tid & 31;
    const int L    = seq_len[b];

    // stage sigmoid(logits[b,:]) into smem (coalesced float4)
    {
        const float4* src = reinterpret_cast<const float4*>(logits + b * TT);
        #pragma unroll
        for (int k = 0; k < (TT / 4) / THREADS; k++) {
            const float4 x = src[tid + k * THREADS];
            float4 s;
            s.x = __fdividef(1.0f, 1.0f + __expf(-x.x));
            s.y = __fdividef(1.0f, 1.0f + __expf(-x.y));
            s.z = __fdividef(1.0f, 1.0f + __expf(-x.z));
            s.w = __fdividef(1.0f, 1.0f + __expf(-x.w));
            reinterpret_cast<float4*>(s_scores)[tid + k * THREADS] = s;
        }
    }
    __syncthreads();   // the ONLY block barrier

    const int i = blockIdx.x * WPB + warp;            // this warp's row
    float* orow = out + ((size_t)b * TT + (size_t)i) * TT;

    if (i >= L) {
        // invalid row -> zeros; pure streaming stores, warp-independent
        const float4 z = make_float4(0.f, 0.f, 0.f, 0.f);
        #pragma unroll
        for (int k = 0; k < 16; k++)
            __stcs(reinterpret_cast<float4*>(orow) + k * 32 + lane, z);
        return;
    }

    const float s_i = s_scores[i];
    float e[64];
    float psum = 0.f;

    // chunk k covers j in [k*128, k*128+128) across the warp (warp-uniform bounds)
    #pragma unroll
    for (int k = 0; k < 16; k++) {
        const int fidx  = k * 32 + lane;     // float4 index
        const int jbase = fidx * 4;
        if ((k + 1) * 128 <= L) {
            // fully valid chunk: no predication
            const float4 sv = reinterpret_cast<const float4*>(s_scores)[fidx];
            const float sj[4] = {sv.x, sv.y, sv.z, sv.w};
            #pragma unroll
            for (int q = 0; q < 4; q++) {
                const float x   = fmaf(-10.0f, fabsf(s_i - sj[q]), 5.0f);
                const float sig = __fdividef(1.0f, 1.0f + __expf(-x));
                const float ev  = __expf(sig);
                e[k * 4 + q] = ev;
                psum += ev;
            }
        } else if (k * 128 >= L) {
            // fully invalid chunk: skip all math
            #pragma unroll
            for (int q = 0; q < 4; q++) e[k * 4 + q] = 0.f;
        } else {
            // straddling chunk (at most one per row): per-element predication
            #pragma unroll
            for (int q = 0; q < 4; q++) {
                const int j = jbase + q;
                float ev = 0.f;
                if (j < L) {
                    const float sj  = s_scores[j];
                    const float x   = fmaf(-10.0f, fabsf(s_i - sj), 5.0f);
                    const float sig = __fdividef(1.0f, 1.0f + __expf(-x));
                    ev = __expf(sig);
                }
                e[k * 4 + q] = ev;
                psum += ev;
            }
        }
    }

    // warp-local butterfly reduction -> every lane has the row sum
    #pragma unroll
    for (int off = 16; off > 0; off >>= 1)
        psum += __shfl_xor_sync(0xFFFFFFFFu, psum, off);
    const float inv = __fdividef(1.0f, psum);

    // normalized streaming stores (float4, coalesced per chunk)
    #pragma unroll
    for (int k = 0; k < 16; k++) {
        const float4 v = make_float4(e[k * 4 + 0] * inv, e[k * 4 + 1] * inv,
                                     e[k * 4 + 2] * inv, e[k * 4 + 3] * inv);
        __stcs(reinterpret_cast<float4*>(orow) + k * 32 + lane, v);
    }
}

extern "C" void kernel_launch(void* const* d_in, const int* in_sizes, int n_in,
                              void* d_out, int out_size) {
    const float* logits  = (const float*)d_in[0];   // [16, 2048, 1] fp32
    const int*   seq_len = (const int*)d_in[1];     // [16] i32
    float*       out     = (float*)d_out;           // [16, 2048, 2048] fp32

    dim3 grid(TT / WPB, BB);
    fused_kernel<<<grid, THREADS>>>(logits, seq_len, out);
}

// round 6
// speedup vs baseline: 1.1892x; 1.0383x over previous
#include <cuda_runtime.h>
#include <cstdint>

// logits [16, 2048, 1] fp32, seq_len [16] i32, out [16, 2048, 2048] fp32.
#define BB 16
#define TT 2048
#define WPB 8                 // warps per block; one output row per warp
#define THREADS (WPB * 32)

// Write-bandwidth-floor kernel (268 MB output @ ~6.2 TB/s effective => ~43.5us).
// Each block: if all its rows are masked (row0 >= L, ~half of blocks on
// average), skip logits staging entirely and stream zeros immediately.
// Otherwise: stage sigmoid(logits[b,:]) to smem once (single barrier), then
// each WARP independently computes one row (regs), warp-shfl reduction,
// streaming float4 stores.
//
// Max-free softmax is exact: rel values in (0.0067, 0.9933) -> exp in (1, e),
// no overflow; masked entries exactly 0, matching the reference's fp32
// exp(-1e9 - max) == 0.
__global__ __launch_bounds__(THREADS, 3) void fused_kernel(
    const float* __restrict__ logits,
    const int* __restrict__ seq_len,
    float* __restrict__ out)
{
    __shared__ float s_scores[TT];

    const int b    = blockIdx.y;
    const int tid  = threadIdx.x;
    const int warp = tid >> 5;
    const int lane = tid & 31;
    const int L    = seq_len[b];
    const int row0 = blockIdx.x * WPB;

    // ---- fast path: whole block is masked rows -> pure zero stream ----
    if (row0 >= L) {
        const float4 z = make_float4(0.f, 0.f, 0.f, 0.f);
        float* oblk = out + ((size_t)b * TT + (size_t)row0) * TT;
        // 8 rows * 2048 floats = 4096 float4; 16 per thread, coalesced
        #pragma unroll
        for (int k = 0; k < 16; k++)
            __stcs(reinterpret_cast<float4*>(oblk) + k * THREADS + tid, z);
        return;
    }

    // ---- stage sigmoid(logits[b,:]) into smem (coalesced float4) ----
    {
        const float4* src = reinterpret_cast<const float4*>(logits + b * TT);
        #pragma unroll
        for (int k = 0; k < (TT / 4) / THREADS; k++) {
            const float4 x = src[tid + k * THREADS];
            float4 s;
            s.x = __fdividef(1.0f, 1.0f + __expf(-x.x));
            s.y = __fdividef(1.0f, 1.0f + __expf(-x.y));
            s.z = __fdividef(1.0f, 1.0f + __expf(-x.z));
            s.w = __fdividef(1.0f, 1.0f + __expf(-x.w));
            reinterpret_cast<float4*>(s_scores)[tid + k * THREADS] = s;
        }
    }
    __syncthreads();   // the ONLY block barrier

    const int i = row0 + warp;                        // this warp's row
    float* orow = out + ((size_t)b * TT + (size_t)i) * TT;

    if (i >= L) {
        // masked row within a partially-valid block -> zeros
        const float4 z = make_float4(0.f, 0.f, 0.f, 0.f);
        #pragma unroll
        for (int k = 0; k < 16; k++)
            __stcs(reinterpret_cast<float4*>(orow) + k * 32 + lane, z);
        return;
    }

    const float s_i = s_scores[i];
    float e[64];
    float psum = 0.f;

    // chunk k covers j in [k*128, k*128+128) across the warp (warp-uniform bounds)
    #pragma unroll
    for (int k = 0; k < 16; k++) {
        const int fidx  = k * 32 + lane;     // float4 index
        const int jbase = fidx * 4;
        if ((k + 1) * 128 <= L) {
            // fully valid chunk: no predication
            const float4 sv = reinterpret_cast<const float4*>(s_scores)[fidx];
            const float sj[4] = {sv.x, sv.y, sv.z, sv.w};
            #pragma unroll
            for (int q = 0; q < 4; q++) {
                const float x   = fmaf(-10.0f, fabsf(s_i - sj[q]), 5.0f);
                const float sig = __fdividef(1.0f, 1.0f + __expf(-x));
                const float ev  = __expf(sig);
                e[k * 4 + q] = ev;
                psum += ev;
            }
        } else if (k * 128 >= L) {
            // fully invalid chunk: skip all math
            #pragma unroll
            for (int q = 0; q < 4; q++) e[k * 4 + q] = 0.f;
        } else {
            // straddling chunk (at most one per row): per-element predication
            #pragma unroll
            for (int q = 0; q < 4; q++) {
                const int j = jbase + q;
                float ev = 0.f;
                if (j < L) {
                    const float sj  = s_scores[j];
                    const float x   = fmaf(-10.0f, fabsf(s_i - sj), 5.0f);
                    const float sig = __fdividef(1.0f, 1.0f + __expf(-x));
                    ev = __expf(sig);
                }
                e[k * 4 + q] = ev;
                psum += ev;
            }
        }
    }

    // warp-local butterfly reduction -> every lane has the row sum
    #pragma unroll
    for (int off = 16; off > 0; off >>= 1)
        psum += __shfl_xor_sync(0xFFFFFFFFu, psum, off);
    const float inv = __fdividef(1.0f, psum);

    // normalized streaming stores (float4, coalesced per chunk)
    #pragma unroll
    for (int k = 0; k < 16; k++) {
        const float4 v = make_float4(e[k * 4 + 0] * inv, e[k * 4 + 1] * inv,
                                     e[k * 4 + 2] * inv, e[k * 4 + 3] * inv);
        __stcs(reinterpret_cast<float4*>(orow) + k * 32 + lane, v);
    }
}

extern "C" void kernel_launch(void* const* d_in, const int* in_sizes, int n_in,
                              void* d_out, int out_size) {
    const float* logits  = (const float*)d_in[0];   // [16, 2048, 1] fp32
    const int*   seq_len = (const int*)d_in[1];     // [16] i32
    float*       out     = (float*)d_out;           // [16, 2048, 2048] fp32

    dim3 grid(TT / WPB, BB);
    fused_kernel<<<grid, THREADS>>>(logits, seq_len, out);
}